// round 13
// baseline (speedup 1.0000x reference)
#include <cuda_runtime.h>

// Problem constants (fixed by reference setup_inputs)
#define Hh     32
#define TIN    999        // teacher-forced steps
#define STEPS  1999       // TIN + future(1000)
#define BATCH  1024

typedef unsigned long long u64;

// Inter-kernel handoff buffers (device globals — allowed scratch)
__device__ float H1g[(size_t)BATCH * TIN * Hh];   // h1 history (TF)  ~131 MB
__device__ float H2g[(size_t)BATCH * TIN * Hh];   // h2 history (TF)  ~131 MB
__device__ float S_h1[BATCH * Hh], S_c1[BATCH * Hh];
__device__ float S_h2[BATCH * Hh], S_c2[BATCH * Hh];

// Packed 2xfp32 FMA / ADD (sm_103a f32x2 pipe)
__device__ __forceinline__ u64 fma2(u64 a, u64 b, u64 c) {
    u64 d;
    asm("fma.rn.f32x2 %0, %1, %2, %3;" : "=l"(d) : "l"(a), "l"(b), "l"(c));
    return d;
}
__device__ __forceinline__ u64 add2(u64 a, u64 b) {
    u64 d;
    asm("add.rn.f32x2 %0, %1, %2;" : "=l"(d) : "l"(a), "l"(b));
    return d;
}
__device__ __forceinline__ float f2lo(u64 a) { return __uint_as_float((unsigned)a); }
__device__ __forceinline__ float f2hi(u64 a) { return __uint_as_float((unsigned)(a >> 32)); }

__device__ __forceinline__ float ex2a(float x) { float y; asm("ex2.approx.f32 %0, %1;" : "=f"(y) : "f"(x)); return y; }
__device__ __forceinline__ float rcpa(float x) { float y; asm("rcp.approx.f32 %0, %1;" : "=f"(y) : "f"(x)); return y; }

// sigmoid(x) = 1/(1 + 2^(-x*log2e)); ~1e-7 accurate
__device__ __forceinline__ float sigm(float x) {
    return rcpa(1.0f + ex2a(-1.4426950408889634f * x));
}
// tanh(x) = 1 - 2/(1 + 2^(2x*log2e)); ~1e-7 accurate
__device__ __forceinline__ float tanh_(float x) {
    return fmaf(-2.0f, rcpa(1.0f + ex2a(2.8853900817779268f * x)), 1.0f);
}

// ===================== Kernel 1: layer-1 scan (TF phase) =====================
// One block per batch element. 7 blocks/SM resident (low regs), 2 barriers/step.
__global__ __launch_bounds__(128, 7) void l1_scan(
    const float* __restrict__ input,
    const float* __restrict__ W_ih1, const float* __restrict__ W_hh1,
    const float* __restrict__ b_ih1, const float* __restrict__ b_hh1)
{
    __shared__ float sh_in[TIN];
    __shared__ __align__(16) float sh_h1[Hh];
    __shared__ float sh_z[4 * Hh];

    const int r = threadIdx.x;           // gate row
    const int b = blockIdx.x;            // batch element

    const float wih1 = W_ih1[r];
    const float bb1  = b_ih1[r] + b_hh1[r];
    u64 whh1p[Hh / 2];
    {
        const u64* p1 = (const u64*)(W_hh1 + r * Hh);
#pragma unroll
        for (int i = 0; i < Hh / 2; i++) whh1p[i] = p1[i];
    }

    for (int t = r; t < TIN; t += 128) sh_in[t] = input[b * TIN + t];

    const bool comb = ((r & 3) == 0);    // 32 combine threads, 8 per warp
    const int  j    = r >> 2;            // owned hidden unit
    if (comb) sh_h1[j] = 0.0f;
    float cst = 0.0f;
    __syncthreads();

#pragma unroll 1
    for (int t = 0; t < TIN; t++) {
        // dot: z1[r] = wih1*x + W_hh1[r,:]@h1 + bb1
        {
            const ulonglong2* hp = (const ulonglong2*)sh_h1;
            u64 a0 = 0ull, a1 = 0ull;
#pragma unroll
            for (int i = 0; i < 8; i++) {
                ulonglong2 hv = hp[i];
                a0 = fma2(whh1p[2 * i],     hv.x, a0);
                a1 = fma2(whh1p[2 * i + 1], hv.y, a1);
            }
            u64 s = add2(a0, a1);
            sh_z[r] = fmaf(wih1, sh_in[t], bb1) + (f2lo(s) + f2hi(s));
        }
        __syncthreads();

        if (comb) {
            float zi = sh_z[j],          zf = sh_z[Hh + j];
            float zg = sh_z[2 * Hh + j], zo = sh_z[3 * Hh + j];
            float cn = fmaf(sigm(zf), cst, sigm(zi) * tanh_(zg));
            cst = cn;
            float hn = sigm(zo) * tanh_(cn);
            sh_h1[j] = hn;
            H1g[((size_t)b * TIN + t) * Hh + j] = hn;
        }
        __syncthreads();
    }

    if (comb) {
        S_h1[b * Hh + j] = sh_h1[j];
        S_c1[b * Hh + j] = cst;
    }
}

// ===================== Kernel 2: layer-2 scan (TF phase) =====================
// EPB=2, grid=512; reads h1 history with distance-2 prefetch; 2 barriers/step.
__global__ __launch_bounds__(128, 4) void l2_scan(
    const float* __restrict__ W_ih2, const float* __restrict__ W_hh2,
    const float* __restrict__ b_ih2, const float* __restrict__ b_hh2)
{
    __shared__ __align__(16) float sh_h1b[2][2][Hh];   // double-buffered h1(t)
    __shared__ __align__(16) float sh_h2[2][Hh];
    __shared__ float sh_z[2][4 * Hh];

    const int r  = threadIdx.x;
    const int b0 = blockIdx.x * 2;

    const float bb2 = b_ih2[r] + b_hh2[r];
    u64 wih2p[Hh / 2], whh2p[Hh / 2];
    {
        const u64* p2 = (const u64*)(W_ih2 + r * Hh);
        const u64* p3 = (const u64*)(W_hh2 + r * Hh);
#pragma unroll
        for (int i = 0; i < Hh / 2; i++) { wih2p[i] = p2[i]; whh2p[i] = p3[i]; }
    }

    const bool comb = ((r & 1) == 0);    // 64 combine threads, 16 per warp
    const int  task = r >> 1;            // 0..63
    const int  te   = task >> 5;         // element
    const int  tj   = task & 31;         // hidden unit
    if (comb) sh_h2[te][tj] = 0.0f;
    float cst = 0.0f;

    // prologue: h1(0) into buf0; prefetch pf = h1(1)
    const int pe = r >> 5;               // r<64: element for prefetch duty
    const int pj = r & 31;
    float pf = 0.0f;
    if (r < 64) {
        sh_h1b[0][pe][pj] = H1g[((size_t)(b0 + pe) * TIN + 0) * Hh + pj];
        pf = H1g[((size_t)(b0 + pe) * TIN + (TIN > 1 ? 1 : 0)) * Hh + pj];
    }
    __syncthreads();

#pragma unroll 1
    for (int t = 0; t < TIN; t++) {
        // install pf = h1(t+1) into the other buffer (nobody reads it this step)
        if (r < 64) sh_h1b[(t + 1) & 1][pe][pj] = pf;
        // issue next prefetch: h1(t+2), clamped
        if (r < 64) {
            int tn = t + 2; if (tn > TIN - 1) tn = TIN - 1;
            pf = H1g[((size_t)(b0 + pe) * TIN + tn) * Hh + pj];
        }

        // dot: z2[e][r] = W_ih2[r,:]@h1(t) + W_hh2[r,:]@h2(t-1) + bb2
#pragma unroll
        for (int e = 0; e < 2; e++) {
            const ulonglong2* h1p = (const ulonglong2*)sh_h1b[t & 1][e];
            const ulonglong2* h2p = (const ulonglong2*)sh_h2[e];
            u64 a0 = 0ull, a1 = 0ull, a2 = 0ull, a3 = 0ull;
#pragma unroll
            for (int i = 0; i < 8; i++) {
                ulonglong2 hv1 = h1p[i];
                ulonglong2 hv2 = h2p[i];
                a0 = fma2(wih2p[2 * i],     hv1.x, a0);
                a1 = fma2(wih2p[2 * i + 1], hv1.y, a1);
                a2 = fma2(whh2p[2 * i],     hv2.x, a2);
                a3 = fma2(whh2p[2 * i + 1], hv2.y, a3);
            }
            u64 s = add2(add2(a0, a1), add2(a2, a3));
            sh_z[e][r] = bb2 + (f2lo(s) + f2hi(s));
        }
        __syncthreads();

        if (comb) {
            float zi = sh_z[te][tj],          zf = sh_z[te][Hh + tj];
            float zg = sh_z[te][2 * Hh + tj], zo = sh_z[te][3 * Hh + tj];
            float cn = fmaf(sigm(zf), cst, sigm(zi) * tanh_(zg));
            cst = cn;
            float hn = sigm(zo) * tanh_(cn);
            sh_h2[te][tj] = hn;
            H2g[((size_t)(b0 + te) * TIN + t) * Hh + tj] = hn;
        }
        __syncthreads();
    }

    if (comb) {
        S_h2[(b0 + te) * Hh + tj] = sh_h2[te][tj];
        S_c2[(b0 + te) * Hh + tj] = cst;
    }
}

// ===================== Kernel 3: autoregressive phase =====================
// Champion gen loop (R11): 3 barriers/step, feedback recomputed in P2.
__global__ __launch_bounds__(128, 4) void gen_kernel(
    const float* __restrict__ W_ih1, const float* __restrict__ W_hh1,
    const float* __restrict__ b_ih1, const float* __restrict__ b_hh1,
    const float* __restrict__ W_ih2, const float* __restrict__ W_hh2,
    const float* __restrict__ b_ih2, const float* __restrict__ b_hh2,
    const float* __restrict__ W_lin, const float* __restrict__ b_lin,
    float* __restrict__ out)
{
    __shared__ __align__(16) float sh_h1[2][Hh];
    __shared__ __align__(16) float sh_h2[2][Hh];
    __shared__ float sh_zA[2][4 * Hh];
    __shared__ float sh_zB[2][4 * Hh];
    __shared__ __align__(16) float sh_wl[Hh];
    __shared__ float sh_wih1[4 * Hh];

    const int r    = threadIdx.x;
    const int lane = r & 31;
    const int w    = r >> 5;
    const int b0   = blockIdx.x * 2;

    const bool is1 = (w < 2);
    const int  ce  = is1 ? w : (w - 2);
    const int  cj  = lane;

    const float wih1 = W_ih1[r];
    const float bb1  = b_ih1[r] + b_hh1[r];
    const float bb2  = b_ih2[r] + b_hh2[r];
    const float blin = b_lin[0];

    u64 whh1p[Hh / 2], wih2p[Hh / 2], whh2p[Hh / 2];
    {
        const u64* p1 = (const u64*)(W_hh1 + r * Hh);
        const u64* p2 = (const u64*)(W_ih2 + r * Hh);
        const u64* p3 = (const u64*)(W_hh2 + r * Hh);
#pragma unroll
        for (int i = 0; i < Hh / 2; i++) { whh1p[i] = p1[i]; wih2p[i] = p2[i]; whh2p[i] = p3[i]; }
    }

    if (r < Hh) sh_wl[r] = W_lin[r];
    sh_wih1[r] = wih1;

    // state load
    if (r < 64) {
        int e = r >> 5, j = r & 31;
        sh_h1[e][j] = S_h1[(b0 + e) * Hh + j];
        sh_h2[e][j] = S_h2[(b0 + e) * Hh + j];
    }
    float cst = is1 ? S_c1[(b0 + ce) * Hh + cj] : S_c2[(b0 + ce) * Hh + cj];
    __syncthreads();

#pragma unroll 1
    for (int t = TIN; t < STEPS; t++) {
        // P1: x-independent hh1 partial
#pragma unroll
        for (int e = 0; e < 2; e++) {
            const ulonglong2* hp = (const ulonglong2*)sh_h1[e];
            u64 a0 = 0ull, a1 = 0ull;
#pragma unroll
            for (int i = 0; i < 8; i++) {
                ulonglong2 hv = hp[i];
                a0 = fma2(whh1p[2 * i],     hv.x, a0);
                a1 = fma2(whh1p[2 * i + 1], hv.y, a1);
            }
            u64 s = add2(a0, a1);
            sh_zA[e][r] = bb1 + (f2lo(s) + f2hi(s));
        }
        __syncthreads();                 // A

        // P2 (warps 0-1): x = W_lin@h2(t-1)+b, emit out[t-1], fold, combine L1
        if (is1) {
            const ulonglong2* wp = (const ulonglong2*)sh_wl;
            const ulonglong2* hp = (const ulonglong2*)sh_h2[ce];
            u64 a0 = 0ull, a1 = 0ull;
#pragma unroll
            for (int i = 0; i < 8; i++) {
                ulonglong2 wv = wp[i];
                ulonglong2 hv = hp[i];
                a0 = fma2(wv.x, hv.x, a0);
                a1 = fma2(wv.y, hv.y, a1);
            }
            u64 sx = add2(a0, a1);
            float x = (f2lo(sx) + f2hi(sx)) + blin;              // == out(t-1)
            if (cj == 0) out[(size_t)(b0 + ce) * STEPS + (t - 1)] = x;

            float zi = fmaf(sh_wih1[cj],          x, sh_zA[ce][cj]);
            float zf = fmaf(sh_wih1[Hh + cj],     x, sh_zA[ce][Hh + cj]);
            float zg = fmaf(sh_wih1[2 * Hh + cj], x, sh_zA[ce][2 * Hh + cj]);
            float zo = fmaf(sh_wih1[3 * Hh + cj], x, sh_zA[ce][3 * Hh + cj]);
            float cn = fmaf(sigm(zf), cst, sigm(zi) * tanh_(zg));
            cst = cn;
            sh_h1[ce][cj] = sigm(zo) * tanh_(cn);
        }
        __syncthreads();                 // B

        // P3: layer-2 dots
#pragma unroll
        for (int e = 0; e < 2; e++) {
            const ulonglong2* h1p = (const ulonglong2*)sh_h1[e];
            const ulonglong2* h2p = (const ulonglong2*)sh_h2[e];
            u64 a0 = 0ull, a1 = 0ull, a2 = 0ull, a3 = 0ull;
#pragma unroll
            for (int i = 0; i < 8; i++) {
                ulonglong2 hv1 = h1p[i];
                ulonglong2 hv2 = h2p[i];
                a0 = fma2(wih2p[2 * i],     hv1.x, a0);
                a1 = fma2(wih2p[2 * i + 1], hv1.y, a1);
                a2 = fma2(whh2p[2 * i],     hv2.x, a2);
                a3 = fma2(whh2p[2 * i + 1], hv2.y, a3);
            }
            u64 s = add2(add2(a0, a1), add2(a2, a3));
            sh_zB[e][r] = bb2 + (f2lo(s) + f2hi(s));
        }
        __syncthreads();                 // C

        // P4 (warps 2-3): combine L2 -> h2(t)
        if (!is1) {
            float zi = sh_zB[ce][cj],          zf = sh_zB[ce][Hh + cj];
            float zg = sh_zB[ce][2 * Hh + cj], zo = sh_zB[ce][3 * Hh + cj];
            float cn = fmaf(sigm(zf), cst, sigm(zi) * tanh_(zg));
            cst = cn;
            sh_h2[ce][cj] = sigm(zo) * tanh_(cn);
        }
    }

    // Final output: out[STEPS-1] = W_lin @ h2(final) + b_lin
    __syncthreads();
    if (is1 && cj == 0) {
        const ulonglong2* wp = (const ulonglong2*)sh_wl;
        const ulonglong2* hp = (const ulonglong2*)sh_h2[ce];
        u64 a0 = 0ull, a1 = 0ull;
#pragma unroll
        for (int i = 0; i < 8; i++) {
            ulonglong2 wv = wp[i];
            ulonglong2 hv = hp[i];
            a0 = fma2(wv.x, hv.x, a0);
            a1 = fma2(wv.y, hv.y, a1);
        }
        u64 sx = add2(a0, a1);
        out[(size_t)(b0 + ce) * STEPS + (STEPS - 1)] = (f2lo(sx) + f2hi(sx)) + blin;
    }
}

// ===================== Kernel 4: TF head =====================
__global__ __launch_bounds__(256) void head_kernel(
    const float* __restrict__ W_lin, const float* __restrict__ b_lin,
    float* __restrict__ out)
{
    const int b = blockIdx.x;
    float4 wv[8];
    const float4* wp = (const float4*)W_lin;
#pragma unroll
    for (int i = 0; i < 8; i++) wv[i] = wp[i];
    const float bl = b_lin[0];

    for (int t = threadIdx.x; t < TIN; t += 256) {
        const float4* hp = (const float4*)(H2g + ((size_t)b * TIN + t) * Hh);
        float acc = bl;
#pragma unroll
        for (int i = 0; i < 8; i++) {
            float4 h = hp[i];
            acc += wv[i].x * h.x + wv[i].y * h.y + wv[i].z * h.z + wv[i].w * h.w;
        }
        out[(size_t)b * STEPS + t] = acc;
    }
}

extern "C" void kernel_launch(void* const* d_in, const int* in_sizes, int n_in,
                              void* d_out, int out_size) {
    const float* input = (const float*)d_in[0];
    const float* W_ih1 = (const float*)d_in[1];
    const float* W_hh1 = (const float*)d_in[2];
    const float* b_ih1 = (const float*)d_in[3];
    const float* b_hh1 = (const float*)d_in[4];
    const float* W_ih2 = (const float*)d_in[5];
    const float* W_hh2 = (const float*)d_in[6];
    const float* b_ih2 = (const float*)d_in[7];
    const float* b_hh2 = (const float*)d_in[8];
    const float* W_lin = (const float*)d_in[9];
    const float* b_lin = (const float*)d_in[10];
    float* out = (float*)d_out;

    l1_scan<<<BATCH, 128>>>(input, W_ih1, W_hh1, b_ih1, b_hh1);
    l2_scan<<<BATCH / 2, 128>>>(W_ih2, W_hh2, b_ih2, b_hh2);
    gen_kernel<<<BATCH / 2, 128>>>(W_ih1, W_hh1, b_ih1, b_hh1,
                                   W_ih2, W_hh2, b_ih2, b_hh2,
                                   W_lin, b_lin, out);
    head_kernel<<<BATCH, 256>>>(W_lin, b_lin, out);
}